// round 2
// baseline (speedup 1.0000x reference)
#include <cuda_runtime.h>
#include <math.h>

// Problem constants (fixed by dataset)
#define NN   50000
#define EE   1600000
#define ET   (EE + NN)      // edges + self loops
#define INC  256
#define HC   128            // HEADS*C
#define H1   4
#define C1   32
#define BN_EPS 1e-5f

// ---------------- scratch (__device__ globals; no cudaMalloc allowed) ----------------
__device__ float g_xs1 [NN * HC];     // x @ W1
__device__ float g_out1[NN * HC];     // layer1 aggregate -> (in-place) h1 after bn/elu
__device__ float g_xs2 [NN * C1];     // h1 @ W2
__device__ float g_out2[NN * C1];     // layer2 aggregate
__device__ float g_als1[NN * H1];
__device__ float g_ald1[NN * H1];
__device__ float g_als2[NN];
__device__ float g_ald2[NN];
__device__ int   g_deg   [NN];
__device__ int   g_rowptr[NN + 1];
__device__ int   g_cursor[NN];
__device__ int   g_csrc[ET];
__device__ float g_cea [ET];
__device__ float g_partial[512];
__device__ float g_mean;
__device__ float g_k1[H1];
__device__ float g_k2;

// ---------------- CSR build ----------------
__global__ void init_deg_kernel() {
    int i = blockIdx.x * blockDim.x + threadIdx.x;
    if (i < NN) g_deg[i] = 1;   // self loop
}

__global__ void hist_kernel(const int* __restrict__ ei) {
    for (int e = blockIdx.x * blockDim.x + threadIdx.x; e < EE; e += gridDim.x * blockDim.x) {
        int d = ei[EE + e];
        atomicAdd(&g_deg[d], 1);
    }
}

__global__ void mean_part_kernel(const float* __restrict__ ea) {
    __shared__ float s[256];
    float v = 0.f;
    for (int i = blockIdx.x * blockDim.x + threadIdx.x; i < EE; i += gridDim.x * blockDim.x)
        v += ea[i];
    s[threadIdx.x] = v; __syncthreads();
    for (int o = 128; o > 0; o >>= 1) {
        if (threadIdx.x < o) s[threadIdx.x] += s[threadIdx.x + o];
        __syncthreads();
    }
    if (threadIdx.x == 0) g_partial[blockIdx.x] = s[0];
}

__global__ void mean_fin_kernel(const float* __restrict__ We1, const float* __restrict__ ae1,
                                const float* __restrict__ We2, const float* __restrict__ ae2) {
    __shared__ float s[512];
    int t = threadIdx.x;
    s[t] = g_partial[t]; __syncthreads();
    for (int o = 256; o > 0; o >>= 1) {
        if (t < o) s[t] += s[t + o];
        __syncthreads();
    }
    if (t == 0) g_mean = s[0] / (float)EE;
    if (t < H1) {
        float k = 0.f;
        for (int c = 0; c < C1; c++) k += We1[t * C1 + c] * ae1[t * C1 + c];
        g_k1[t] = k;
    }
    if (t == H1) {
        float k = 0.f;
        for (int c = 0; c < C1; c++) k += We2[c] * ae2[c];
        g_k2 = k;
    }
}

__global__ void scan_kernel() {
    __shared__ int s[1024];
    const int T = 1024;
    int t = threadIdx.x;
    int chunk = (NN + T - 1) / T;
    int lo = t * chunk;
    int hi = lo + chunk; if (hi > NN) hi = NN;
    int sum = 0;
    for (int i = lo; i < hi; i++) sum += g_deg[i];
    s[t] = sum; __syncthreads();
    for (int off = 1; off < T; off <<= 1) {
        int v = (t >= off) ? s[t - off] : 0;
        __syncthreads();
        s[t] += v;
        __syncthreads();
    }
    int run = s[t] - sum;  // exclusive prefix
    for (int i = lo; i < hi; i++) {
        g_rowptr[i] = run;
        g_cursor[i] = run;
        run += g_deg[i];
    }
    if (t == T - 1) g_rowptr[NN] = s[T - 1];
}

__global__ void scatter_kernel(const int* __restrict__ ei, const float* __restrict__ ea) {
    float mn = g_mean;
    for (int idx = blockIdx.x * blockDim.x + threadIdx.x; idx < ET; idx += gridDim.x * blockDim.x) {
        if (idx < EE) {
            int srcn = ei[idx];
            int dstn = ei[EE + idx];
            int slot = atomicAdd(&g_cursor[dstn], 1);
            g_csrc[slot] = srcn;
            g_cea[slot]  = ea[idx];
        } else {
            int n = idx - EE;
            int slot = atomicAdd(&g_cursor[n], 1);
            g_csrc[slot] = n;
            g_cea[slot]  = mn;
        }
    }
}

// ---------------- GEMM1: [NN,256] @ [256,128] -> g_xs1 ----------------
__global__ void sgemm1_kernel(const float* __restrict__ A, const float* __restrict__ B) {
    // BM=128, BN=128 (=full N), BK=8, TM=8, TN=8, 256 threads
    const int K = INC, Nn = HC;
    __shared__ float As[8][128];
    __shared__ float Bs[8][128];
    int tid  = threadIdx.x;
    int brow = blockIdx.x;
    int trow = (tid / 16) * 8;
    int tcol = (tid % 16) * 8;
    int rowA = tid / 2,  colA = (tid % 2) * 4;
    int rowB = tid / 32, colB = (tid % 32) * 4;
    int ag = brow * 128 + rowA;

    float acc[8][8];
#pragma unroll
    for (int i = 0; i < 8; i++)
#pragma unroll
        for (int j = 0; j < 8; j++) acc[i][j] = 0.f;

    for (int k0 = 0; k0 < K; k0 += 8) {
        float4 av = make_float4(0.f, 0.f, 0.f, 0.f);
        if (ag < NN) av = *(const float4*)(A + (size_t)ag * K + k0 + colA);
        As[colA + 0][rowA] = av.x;
        As[colA + 1][rowA] = av.y;
        As[colA + 2][rowA] = av.z;
        As[colA + 3][rowA] = av.w;
        float4 bv = *(const float4*)(B + (size_t)(k0 + rowB) * Nn + colB);
        *(float4*)(&Bs[rowB][colB]) = bv;
        __syncthreads();
#pragma unroll
        for (int kk = 0; kk < 8; kk++) {
            float ar[8], br[8];
#pragma unroll
            for (int i = 0; i < 8; i++) ar[i] = As[kk][trow + i];
#pragma unroll
            for (int j = 0; j < 8; j++) br[j] = Bs[kk][tcol + j];
#pragma unroll
            for (int i = 0; i < 8; i++)
#pragma unroll
                for (int j = 0; j < 8; j++) acc[i][j] += ar[i] * br[j];
        }
        __syncthreads();
    }
#pragma unroll
    for (int i = 0; i < 8; i++) {
        int r = brow * 128 + trow + i;
        if (r < NN) {
            float* cp = g_xs1 + (size_t)r * Nn + tcol;
            *(float4*)(cp)     = make_float4(acc[i][0], acc[i][1], acc[i][2], acc[i][3]);
            *(float4*)(cp + 4) = make_float4(acc[i][4], acc[i][5], acc[i][6], acc[i][7]);
        }
    }
}

// ---------------- attention coefficients ----------------
__global__ void al1_kernel(const float* __restrict__ as1, const float* __restrict__ ad1) {
    int idx = blockIdx.x * blockDim.x + threadIdx.x;
    if (idx >= NN * H1) return;
    int n = idx >> 2, h = idx & 3;
    const float* xp = g_xs1 + (size_t)n * HC + h * C1;
    float s = 0.f, d = 0.f;
#pragma unroll
    for (int c = 0; c < C1; c++) {
        float v = xp[c];
        s += v * as1[h * C1 + c];
        d += v * ad1[h * C1 + c];
    }
    g_als1[idx] = s;
    g_ald1[idx] = d;
}

__global__ void al2_kernel(const float* __restrict__ as2, const float* __restrict__ ad2) {
    int n = blockIdx.x * blockDim.x + threadIdx.x;
    if (n >= NN) return;
    const float* xp = g_xs2 + (size_t)n * C1;
    float s = 0.f, d = 0.f;
#pragma unroll
    for (int c = 0; c < C1; c++) {
        float v = xp[c];
        s += v * as2[c];
        d += v * ad2[c];
    }
    g_als2[n] = s;
    g_ald2[n] = d;
}

// ---------------- aggregation (segment softmax + weighted sum) ----------------
__device__ __forceinline__ float leaky(float x) { return x > 0.f ? x : 0.2f * x; }

__global__ void agg1_kernel() {
    int gw   = (blockIdx.x * blockDim.x + threadIdx.x) >> 5;
    int lane = threadIdx.x & 31;
    if (gw >= NN * H1) return;
    int n = gw >> 2, h = gw & 3;
    int beg = g_rowptr[n], end = g_rowptr[n + 1];
    float kh  = g_k1[h];
    float ald = g_ald1[n * H1 + h];

    float m = -1e30f;
    for (int e = beg + lane; e < end; e += 32) {
        int s = g_csrc[e];
        float l = leaky(g_als1[s * H1 + h] + ald + kh * g_cea[e]);
        m = fmaxf(m, l);
    }
#pragma unroll
    for (int off = 16; off > 0; off >>= 1)
        m = fmaxf(m, __shfl_xor_sync(0xffffffffu, m, off));

    float den = 0.f, acc = 0.f;
    for (int e = beg; e < end; ++e) {
        int s = g_csrc[e];
        float l = leaky(g_als1[s * H1 + h] + ald + kh * g_cea[e]);
        float w = __expf(l - m);
        den += w;
        acc += w * g_xs1[(size_t)s * HC + h * C1 + lane];
    }
    g_out1[(size_t)n * HC + h * C1 + lane] = acc / (den + 1e-16f);
}

__global__ void agg2_kernel() {
    int gw   = (blockIdx.x * blockDim.x + threadIdx.x) >> 5;
    int lane = threadIdx.x & 31;
    if (gw >= NN) return;
    int n = gw;
    int beg = g_rowptr[n], end = g_rowptr[n + 1];
    float k2  = g_k2;
    float ald = g_ald2[n];

    float m = -1e30f;
    for (int e = beg + lane; e < end; e += 32) {
        int s = g_csrc[e];
        float l = leaky(g_als2[s] + ald + k2 * g_cea[e]);
        m = fmaxf(m, l);
    }
#pragma unroll
    for (int off = 16; off > 0; off >>= 1)
        m = fmaxf(m, __shfl_xor_sync(0xffffffffu, m, off));

    float den = 0.f, acc = 0.f;
    for (int e = beg; e < end; ++e) {
        int s = g_csrc[e];
        float l = leaky(g_als2[s] + ald + k2 * g_cea[e]);
        float w = __expf(l - m);
        den += w;
        acc += w * g_xs2[(size_t)s * C1 + lane];
    }
    g_out2[(size_t)n * C1 + lane] = acc / (den + 1e-16f);
}

// ---------------- bias + BN(eval) + ELU ----------------
__global__ void bnelu1_kernel(const float* __restrict__ b, const float* __restrict__ g,
                              const float* __restrict__ be) {
    float inv = rsqrtf(1.f + BN_EPS);
    for (int i = blockIdx.x * blockDim.x + threadIdx.x; i < NN * HC; i += gridDim.x * blockDim.x) {
        int c = i & (HC - 1);
        float v = g_out1[i] + b[c];
        v = v * (g[c] * inv) + be[c];
        g_out1[i] = v > 0.f ? v : expm1f(v);
    }
}

__global__ void bnelu2_kernel(const float* __restrict__ b, const float* __restrict__ g,
                              const float* __restrict__ be, float* __restrict__ hout) {
    float inv = rsqrtf(1.f + BN_EPS);
    for (int i = blockIdx.x * blockDim.x + threadIdx.x; i < NN * C1; i += gridDim.x * blockDim.x) {
        int c = i & (C1 - 1);
        float v = g_out2[i] + b[c];
        v = v * (g[c] * inv) + be[c];
        hout[i] = v > 0.f ? v : expm1f(v);
    }
}

// ---------------- GEMM2: [NN,128] @ [128,32] -> g_xs2 ----------------
__global__ void gemm2_kernel(const float* __restrict__ W2) {
    __shared__ float Ws[HC * C1];
    for (int i = threadIdx.x; i < HC * C1; i += blockDim.x) Ws[i] = W2[i];
    __syncthreads();
    int node = blockIdx.x * 8 + threadIdx.x / 32;
    int c    = threadIdx.x & 31;
    if (node >= NN) return;
    const float* row = g_out1 + (size_t)node * HC;
    float s = 0.f;
#pragma unroll 8
    for (int k = 0; k < HC; k++) s += row[k] * Ws[k * C1 + c];
    g_xs2[(size_t)node * C1 + c] = s;
}

// ---------------- classifier + regressor heads ----------------
__global__ void heads_kernel(const float* __restrict__ Wc1, const float* __restrict__ bc1,
                             const float* __restrict__ Wc2, const float* __restrict__ bc2,
                             const float* __restrict__ Wr1, const float* __restrict__ br1,
                             const float* __restrict__ Wr2, const float* __restrict__ br2,
                             float* __restrict__ out) {
    __shared__ float sWc1[C1 * 16], sWr1[C1 * 16];
    __shared__ float sWc2[16 * 2], sWr2[16];
    __shared__ float sbc1[16], sbr1[16], sbc2[2], sbr2v[1];
    int t = threadIdx.x;
    for (int i = t; i < C1 * 16; i += blockDim.x) { sWc1[i] = Wc1[i]; sWr1[i] = Wr1[i]; }
    if (t < 32) sWc2[t] = Wc2[t];
    if (t < 16) { sWr2[t] = Wr2[t]; sbc1[t] = bc1[t]; sbr1[t] = br1[t]; }
    if (t < 2)  sbc2[t] = bc2[t];
    if (t == 0) sbr2v[0] = br2[0];
    __syncthreads();

    int n = blockIdx.x * blockDim.x + t;
    if (n >= NN) return;
    const float* hp = out + 3 * NN + (size_t)n * C1;
    float hv[C1];
#pragma unroll
    for (int c = 0; c < C1; c++) hv[c] = hp[c];

    float c0 = sbc2[0], c1 = sbc2[1];
#pragma unroll
    for (int j = 0; j < 16; j++) {
        float tt = sbc1[j];
#pragma unroll
        for (int c = 0; c < C1; c++) tt += hv[c] * sWc1[c * 16 + j];
        tt = fmaxf(tt, 0.f);
        c0 += tt * sWc2[j * 2 + 0];
        c1 += tt * sWc2[j * 2 + 1];
    }
    float r = sbr2v[0];
#pragma unroll
    for (int j = 0; j < 16; j++) {
        float tt = sbr1[j];
#pragma unroll
        for (int c = 0; c < C1; c++) tt += hv[c] * sWr1[c * 16 + j];
        tt = fmaxf(tt, 0.f);
        r += tt * sWr2[j];
    }
    out[(size_t)n * 2 + 0] = c0;
    out[(size_t)n * 2 + 1] = c1;
    out[2 * NN + n] = r;
}

// ---------------- launch ----------------
extern "C" void kernel_launch(void* const* d_in, const int* in_sizes, int n_in,
                              void* d_out, int out_size) {
    const float* x   = (const float*)d_in[0];
    const int*   ei  = (const int*)d_in[1];     // int32! (JAX x64 disabled)
    const float* ea  = (const float*)d_in[2];
    const float* W1  = (const float*)d_in[3];
    const float* as1 = (const float*)d_in[4];
    const float* ad1 = (const float*)d_in[5];
    const float* We1 = (const float*)d_in[6];
    const float* ae1 = (const float*)d_in[7];
    const float* b1  = (const float*)d_in[8];
    const float* g1  = (const float*)d_in[9];
    const float* be1 = (const float*)d_in[10];
    const float* W2  = (const float*)d_in[11];
    const float* as2 = (const float*)d_in[12];
    const float* ad2 = (const float*)d_in[13];
    const float* We2 = (const float*)d_in[14];
    const float* ae2 = (const float*)d_in[15];
    const float* b2  = (const float*)d_in[16];
    const float* g2  = (const float*)d_in[17];
    const float* be2 = (const float*)d_in[18];
    const float* Wc1 = (const float*)d_in[19];
    const float* bc1 = (const float*)d_in[20];
    const float* Wc2 = (const float*)d_in[21];
    const float* bc2 = (const float*)d_in[22];
    const float* Wr1 = (const float*)d_in[23];
    const float* br1 = (const float*)d_in[24];
    const float* Wr2 = (const float*)d_in[25];
    const float* br2 = (const float*)d_in[26];
    float* out = (float*)d_out;

    // CSR build (reused by both layers)
    init_deg_kernel<<<(NN + 255) / 256, 256>>>();
    hist_kernel<<<2048, 256>>>(ei);
    mean_part_kernel<<<512, 256>>>(ea);
    mean_fin_kernel<<<1, 512>>>(We1, ae1, We2, ae2);
    scan_kernel<<<1, 1024>>>();
    scatter_kernel<<<2048, 256>>>(ei, ea);

    // layer 1
    sgemm1_kernel<<<(NN + 127) / 128, 256>>>(x, W1);
    al1_kernel<<<(NN * H1 + 255) / 256, 256>>>(as1, ad1);
    agg1_kernel<<<(NN * H1 * 32 + 255) / 256, 256>>>();
    bnelu1_kernel<<<4096, 256>>>(b1, g1, be1);

    // layer 2
    gemm2_kernel<<<(NN + 7) / 8, 256>>>(W2);
    al2_kernel<<<(NN + 255) / 256, 256>>>(as2, ad2);
    agg2_kernel<<<(NN * 32 + 255) / 256, 256>>>();
    bnelu2_kernel<<<2048, 256>>>(b2, g2, be2, out + 3 * NN);

    // heads
    heads_kernel<<<(NN + 255) / 256, 256>>>(Wc1, bc1, Wc2, bc2, Wr1, br1, Wr2, br2, out);
}

// round 3
// speedup vs baseline: 1.1294x; 1.1294x over previous
#include <cuda_runtime.h>
#include <math.h>

#define NN   50000
#define EE   1600000
#define ET   (EE + NN)
#define INC  256
#define HC   128
#define H1   4
#define C1   32
#define BN_EPS 1e-5f

typedef unsigned long long ull;

// ---------------- scratch ----------------
__device__ float g_xs1 [NN * HC];
__device__ float g_out1[NN * HC];     // h1 after fused bias+bn+elu
__device__ float g_xs2 [NN * C1];
__device__ float g_als1[NN * H1];
__device__ float g_ald1[NN * H1];
__device__ float g_als2[NN];
__device__ float g_ald2[NN];
__device__ int   g_deg   [NN];
__device__ int   g_rowptr[NN + 1];
__device__ int   g_cursor[NN];
__device__ int2  g_cpair[ET];         // packed (src, edge_attr bits)
__device__ float g_partial[512];
__device__ float g_mean;
__device__ float g_k1[H1];
__device__ float g_k2;

// ---------------- f32x2 helpers ----------------
__device__ __forceinline__ void fma2(ull &d, ull a, ull b) {
    asm("fma.rn.f32x2 %0, %1, %2, %0;" : "+l"(d) : "l"(a), "l"(b));
}
__device__ __forceinline__ ull pack2(float x, float y) {
    ull r; asm("mov.b64 %0, {%1, %2};" : "=l"(r) : "f"(x), "f"(y)); return r;
}
__device__ __forceinline__ float2 unpack2(ull v) {
    float2 f; asm("mov.b64 {%0, %1}, %2;" : "=f"(f.x), "=f"(f.y) : "l"(v)); return f;
}

// ---------------- CSR build ----------------
__global__ void init_deg_kernel() {
    int i = blockIdx.x * blockDim.x + threadIdx.x;
    if (i < NN) g_deg[i] = 1;   // self loop
}

__global__ void hist_mean_kernel(const int* __restrict__ ei, const float* __restrict__ ea) {
    __shared__ float s[256];
    float v = 0.f;
    for (int e = blockIdx.x * blockDim.x + threadIdx.x; e < EE; e += gridDim.x * blockDim.x) {
        atomicAdd(&g_deg[ei[EE + e]], 1);
        v += ea[e];
    }
    s[threadIdx.x] = v; __syncthreads();
    for (int o = 128; o > 0; o >>= 1) {
        if (threadIdx.x < o) s[threadIdx.x] += s[threadIdx.x + o];
        __syncthreads();
    }
    if (threadIdx.x == 0) g_partial[blockIdx.x] = s[0];
}

__global__ void mean_fin_kernel(const float* __restrict__ We1, const float* __restrict__ ae1,
                                const float* __restrict__ We2, const float* __restrict__ ae2) {
    __shared__ float s[512];
    int t = threadIdx.x;
    s[t] = g_partial[t]; __syncthreads();
    for (int o = 256; o > 0; o >>= 1) {
        if (t < o) s[t] += s[t + o];
        __syncthreads();
    }
    if (t == 0) g_mean = s[0] / (float)EE;
    if (t < H1) {
        float k = 0.f;
        for (int c = 0; c < C1; c++) k += We1[t * C1 + c] * ae1[t * C1 + c];
        g_k1[t] = k;
    }
    if (t == H1) {
        float k = 0.f;
        for (int c = 0; c < C1; c++) k += We2[c] * ae2[c];
        g_k2 = k;
    }
}

__global__ void scan_kernel() {
    __shared__ int s[1024];
    const int T = 1024;
    int t = threadIdx.x;
    int chunk = (NN + T - 1) / T;
    int lo = t * chunk;
    int hi = lo + chunk; if (hi > NN) hi = NN;
    int sum = 0;
    for (int i = lo; i < hi; i++) sum += g_deg[i];
    s[t] = sum; __syncthreads();
    for (int off = 1; off < T; off <<= 1) {
        int v = (t >= off) ? s[t - off] : 0;
        __syncthreads();
        s[t] += v;
        __syncthreads();
    }
    int run = s[t] - sum;
    for (int i = lo; i < hi; i++) {
        g_rowptr[i] = run;
        g_cursor[i] = run;
        run += g_deg[i];
    }
    if (t == T - 1) g_rowptr[NN] = s[T - 1];
}

__global__ void scatter_kernel(const int* __restrict__ ei, const float* __restrict__ ea) {
    float mn = g_mean;
    for (int idx = blockIdx.x * blockDim.x + threadIdx.x; idx < ET; idx += gridDim.x * blockDim.x) {
        if (idx < EE) {
            int srcn = ei[idx];
            int dstn = ei[EE + idx];
            int slot = atomicAdd(&g_cursor[dstn], 1);
            g_cpair[slot] = make_int2(srcn, __float_as_int(ea[idx]));
        } else {
            int n = idx - EE;
            int slot = atomicAdd(&g_cursor[n], 1);
            g_cpair[slot] = make_int2(n, __float_as_int(mn));
        }
    }
}

// ---------------- GEMM1: [NN,256] @ [256,128] with f32x2 ----------------
__global__ void sgemm1_kernel(const float* __restrict__ A, const float* __restrict__ B) {
    const int K = INC, Nn = HC;
    __shared__ float As[8][128];
    __shared__ float Bs[8][128];
    int tid  = threadIdx.x;
    int brow = blockIdx.x;
    int trow = (tid / 16) * 8;
    int tcol = (tid % 16) * 8;
    int rowA = tid / 2,  colA = (tid % 2) * 4;
    int rowB = tid / 32, colB = (tid % 32) * 4;
    int ag = brow * 128 + rowA;

    ull acc2[4][8];   // row-pairs (trow+2p, trow+2p+1) x cols (tcol+j)
#pragma unroll
    for (int p = 0; p < 4; p++)
#pragma unroll
        for (int j = 0; j < 8; j++) acc2[p][j] = 0ULL;

    for (int k0 = 0; k0 < K; k0 += 8) {
        float4 av = make_float4(0.f, 0.f, 0.f, 0.f);
        if (ag < NN) av = *(const float4*)(A + (size_t)ag * K + k0 + colA);
        As[colA + 0][rowA] = av.x;
        As[colA + 1][rowA] = av.y;
        As[colA + 2][rowA] = av.z;
        As[colA + 3][rowA] = av.w;
        float4 bv = *(const float4*)(B + (size_t)(k0 + rowB) * Nn + colB);
        *(float4*)(&Bs[rowB][colB]) = bv;
        __syncthreads();
#pragma unroll
        for (int kk = 0; kk < 8; kk++) {
            ull ar2[4];
#pragma unroll
            for (int p = 0; p < 4; p++) {
                float2 a2 = *(const float2*)(&As[kk][trow + 2 * p]);
                ar2[p] = pack2(a2.x, a2.y);
            }
            ull br2[8];
#pragma unroll
            for (int j = 0; j < 8; j++) {
                float b = Bs[kk][tcol + j];
                br2[j] = pack2(b, b);
            }
#pragma unroll
            for (int p = 0; p < 4; p++)
#pragma unroll
                for (int j = 0; j < 8; j++) fma2(acc2[p][j], ar2[p], br2[j]);
        }
        __syncthreads();
    }
#pragma unroll
    for (int p = 0; p < 4; p++) {
        float c0[8], c1[8];
#pragma unroll
        for (int j = 0; j < 8; j++) {
            float2 v = unpack2(acc2[p][j]);
            c0[j] = v.x; c1[j] = v.y;
        }
        int r = brow * 128 + trow + 2 * p;
        if (r < NN) {
            float* cp = g_xs1 + (size_t)r * Nn + tcol;
            *(float4*)(cp)     = make_float4(c0[0], c0[1], c0[2], c0[3]);
            *(float4*)(cp + 4) = make_float4(c0[4], c0[5], c0[6], c0[7]);
        }
        if (r + 1 < NN) {
            float* cp = g_xs1 + (size_t)(r + 1) * Nn + tcol;
            *(float4*)(cp)     = make_float4(c1[0], c1[1], c1[2], c1[3]);
            *(float4*)(cp + 4) = make_float4(c1[4], c1[5], c1[6], c1[7]);
        }
    }
}

// ---------------- attention coefficients (layer 1) ----------------
__global__ void al1_kernel(const float* __restrict__ as1, const float* __restrict__ ad1) {
    int idx = blockIdx.x * blockDim.x + threadIdx.x;
    if (idx >= NN * H1) return;
    int n = idx >> 2, h = idx & 3;
    const float* xp = g_xs1 + (size_t)n * HC + h * C1;
    float s = 0.f, d = 0.f;
#pragma unroll
    for (int c = 0; c < C1; c++) {
        float v = xp[c];
        s += v * as1[h * C1 + c];
        d += v * ad1[h * C1 + c];
    }
    g_als1[idx] = s;
    g_ald1[idx] = d;
}

// ---------------- aggregation: single-pass softmax (no max) + fused bias/bn/elu ----
__device__ __forceinline__ float leaky(float x) { return x > 0.f ? x : 0.2f * x; }
__device__ __forceinline__ float elu(float x)   { return x > 0.f ? x : expm1f(x); }

__global__ void agg1_kernel(const float* __restrict__ b1, const float* __restrict__ g1,
                            const float* __restrict__ be1) {
    int gw   = (blockIdx.x * blockDim.x + threadIdx.x) >> 5;
    int lane = threadIdx.x & 31;
    if (gw >= NN * H1) return;
    int n = gw >> 2, h = gw & 3;
    int beg = g_rowptr[n], end = g_rowptr[n + 1];
    float kh  = g_k1[h];
    float ald = g_ald1[n * H1 + h];
    size_t xoff = (size_t)h * C1 + lane;

    float den = 0.f, acc = 0.f;
    int e = beg;
    for (; e + 4 <= end; e += 4) {
        int2 p0 = g_cpair[e], p1 = g_cpair[e + 1], p2 = g_cpair[e + 2], p3 = g_cpair[e + 3];
        float a0 = g_als1[p0.x * H1 + h];
        float a1 = g_als1[p1.x * H1 + h];
        float a2 = g_als1[p2.x * H1 + h];
        float a3 = g_als1[p3.x * H1 + h];
        float x0 = g_xs1[(size_t)p0.x * HC + xoff];
        float x1 = g_xs1[(size_t)p1.x * HC + xoff];
        float x2 = g_xs1[(size_t)p2.x * HC + xoff];
        float x3 = g_xs1[(size_t)p3.x * HC + xoff];
        float w0 = __expf(fminf(leaky(a0 + ald + kh * __int_as_float(p0.y)), 80.f));
        float w1 = __expf(fminf(leaky(a1 + ald + kh * __int_as_float(p1.y)), 80.f));
        float w2 = __expf(fminf(leaky(a2 + ald + kh * __int_as_float(p2.y)), 80.f));
        float w3 = __expf(fminf(leaky(a3 + ald + kh * __int_as_float(p3.y)), 80.f));
        den += w0 + w1 + w2 + w3;
        acc += w0 * x0 + w1 * x1 + w2 * x2 + w3 * x3;
    }
    for (; e < end; ++e) {
        int2 p = g_cpair[e];
        float w = __expf(fminf(leaky(g_als1[p.x * H1 + h] + ald + kh * __int_as_float(p.y)), 80.f));
        den += w;
        acc += w * g_xs1[(size_t)p.x * HC + xoff];
    }
    int c = h * C1 + lane;
    float v = acc / (den + 1e-16f) + b1[c];
    v = v * (g1[c] * rsqrtf(1.f + BN_EPS)) + be1[c];
    g_out1[(size_t)n * HC + c] = elu(v);
}

__global__ void agg2_kernel(const float* __restrict__ b2, const float* __restrict__ g2,
                            const float* __restrict__ be2, float* __restrict__ hout) {
    int gw   = (blockIdx.x * blockDim.x + threadIdx.x) >> 5;
    int lane = threadIdx.x & 31;
    if (gw >= NN) return;
    int n = gw;
    int beg = g_rowptr[n], end = g_rowptr[n + 1];
    float k2  = g_k2;
    float ald = g_ald2[n];

    float den = 0.f, acc = 0.f;
    int e = beg;
    for (; e + 4 <= end; e += 4) {
        int2 p0 = g_cpair[e], p1 = g_cpair[e + 1], p2 = g_cpair[e + 2], p3 = g_cpair[e + 3];
        float a0 = g_als2[p0.x];
        float a1 = g_als2[p1.x];
        float a2 = g_als2[p2.x];
        float a3 = g_als2[p3.x];
        float x0 = g_xs2[(size_t)p0.x * C1 + lane];
        float x1 = g_xs2[(size_t)p1.x * C1 + lane];
        float x2 = g_xs2[(size_t)p2.x * C1 + lane];
        float x3 = g_xs2[(size_t)p3.x * C1 + lane];
        float w0 = __expf(fminf(leaky(a0 + ald + k2 * __int_as_float(p0.y)), 80.f));
        float w1 = __expf(fminf(leaky(a1 + ald + k2 * __int_as_float(p1.y)), 80.f));
        float w2 = __expf(fminf(leaky(a2 + ald + k2 * __int_as_float(p2.y)), 80.f));
        float w3 = __expf(fminf(leaky(a3 + ald + k2 * __int_as_float(p3.y)), 80.f));
        den += w0 + w1 + w2 + w3;
        acc += w0 * x0 + w1 * x1 + w2 * x2 + w3 * x3;
    }
    for (; e < end; ++e) {
        int2 p = g_cpair[e];
        float w = __expf(fminf(leaky(g_als2[p.x] + ald + k2 * __int_as_float(p.y)), 80.f));
        den += w;
        acc += w * g_xs2[(size_t)p.x * C1 + lane];
    }
    float v = acc / (den + 1e-16f) + b2[lane];
    v = v * (g2[lane] * rsqrtf(1.f + BN_EPS)) + be2[lane];
    hout[(size_t)n * C1 + lane] = elu(v);
}

// ---------------- GEMM2 + fused al2 ----------------
__global__ void gemm2_kernel(const float* __restrict__ W2, const float* __restrict__ as2,
                             const float* __restrict__ ad2) {
    __shared__ float Ws[HC * C1];
    for (int i = threadIdx.x; i < HC * C1; i += blockDim.x) Ws[i] = W2[i];
    __syncthreads();
    int node = blockIdx.x * 8 + threadIdx.x / 32;
    int lane = threadIdx.x & 31;
    if (node >= NN) return;
    const float* row = g_out1 + (size_t)node * HC;
    float s = 0.f;
#pragma unroll 8
    for (int k = 0; k < HC; k++) s += row[k] * Ws[k * C1 + lane];
    g_xs2[(size_t)node * C1 + lane] = s;

    float ps = s * as2[lane];
    float pd = s * ad2[lane];
#pragma unroll
    for (int off = 16; off > 0; off >>= 1) {
        ps += __shfl_xor_sync(0xffffffffu, ps, off);
        pd += __shfl_xor_sync(0xffffffffu, pd, off);
    }
    if (lane == 0) { g_als2[node] = ps; g_ald2[node] = pd; }
}

// ---------------- heads ----------------
__global__ void heads_kernel(const float* __restrict__ Wc1, const float* __restrict__ bc1,
                             const float* __restrict__ Wc2, const float* __restrict__ bc2,
                             const float* __restrict__ Wr1, const float* __restrict__ br1,
                             const float* __restrict__ Wr2, const float* __restrict__ br2,
                             float* __restrict__ out) {
    __shared__ float sWc1[C1 * 16], sWr1[C1 * 16];
    __shared__ float sWc2[16 * 2], sWr2[16];
    __shared__ float sbc1[16], sbr1[16], sbc2[2], sbr2v[1];
    int t = threadIdx.x;
    for (int i = t; i < C1 * 16; i += blockDim.x) { sWc1[i] = Wc1[i]; sWr1[i] = Wr1[i]; }
    if (t < 32) sWc2[t] = Wc2[t];
    if (t < 16) { sWr2[t] = Wr2[t]; sbc1[t] = bc1[t]; sbr1[t] = br1[t]; }
    if (t < 2)  sbc2[t] = bc2[t];
    if (t == 0) sbr2v[0] = br2[0];
    __syncthreads();

    int n = blockIdx.x * blockDim.x + t;
    if (n >= NN) return;
    const float* hp = out + 3 * NN + (size_t)n * C1;
    float hv[C1];
#pragma unroll
    for (int c = 0; c < C1; c++) hv[c] = hp[c];

    float c0 = sbc2[0], c1 = sbc2[1];
#pragma unroll
    for (int j = 0; j < 16; j++) {
        float tt = sbc1[j];
#pragma unroll
        for (int c = 0; c < C1; c++) tt += hv[c] * sWc1[c * 16 + j];
        tt = fmaxf(tt, 0.f);
        c0 += tt * sWc2[j * 2 + 0];
        c1 += tt * sWc2[j * 2 + 1];
    }
    float r = sbr2v[0];
#pragma unroll
    for (int j = 0; j < 16; j++) {
        float tt = sbr1[j];
#pragma unroll
        for (int c = 0; c < C1; c++) tt += hv[c] * sWr1[c * 16 + j];
        tt = fmaxf(tt, 0.f);
        r += tt * sWr2[j];
    }
    out[(size_t)n * 2 + 0] = c0;
    out[(size_t)n * 2 + 1] = c1;
    out[2 * NN + n] = r;
}

// ---------------- launch ----------------
extern "C" void kernel_launch(void* const* d_in, const int* in_sizes, int n_in,
                              void* d_out, int out_size) {
    const float* x   = (const float*)d_in[0];
    const int*   ei  = (const int*)d_in[1];     // int32 (JAX x64 disabled)
    const float* ea  = (const float*)d_in[2];
    const float* W1  = (const float*)d_in[3];
    const float* as1 = (const float*)d_in[4];
    const float* ad1 = (const float*)d_in[5];
    const float* We1 = (const float*)d_in[6];
    const float* ae1 = (const float*)d_in[7];
    const float* b1  = (const float*)d_in[8];
    const float* g1  = (const float*)d_in[9];
    const float* be1 = (const float*)d_in[10];
    const float* W2  = (const float*)d_in[11];
    const float* as2 = (const float*)d_in[12];
    const float* ad2 = (const float*)d_in[13];
    const float* We2 = (const float*)d_in[14];
    const float* ae2 = (const float*)d_in[15];
    const float* b2  = (const float*)d_in[16];
    const float* g2  = (const float*)d_in[17];
    const float* be2 = (const float*)d_in[18];
    const float* Wc1 = (const float*)d_in[19];
    const float* bc1 = (const float*)d_in[20];
    const float* Wc2 = (const float*)d_in[21];
    const float* bc2 = (const float*)d_in[22];
    const float* Wr1 = (const float*)d_in[23];
    const float* br1 = (const float*)d_in[24];
    const float* Wr2 = (const float*)d_in[25];
    const float* br2 = (const float*)d_in[26];
    float* out = (float*)d_out;

    // CSR build (shared by both layers)
    init_deg_kernel<<<(NN + 255) / 256, 256>>>();
    hist_mean_kernel<<<512, 256>>>(ei, ea);
    mean_fin_kernel<<<1, 512>>>(We1, ae1, We2, ae2);
    scan_kernel<<<1, 1024>>>();
    scatter_kernel<<<2048, 256>>>(ei, ea);

    // layer 1
    sgemm1_kernel<<<(NN + 127) / 128, 256>>>(x, W1);
    al1_kernel<<<(NN * H1 + 255) / 256, 256>>>(as1, ad1);
    agg1_kernel<<<(NN * H1) / 8, 256>>>(b1, g1, be1);   // 8 warps/block

    // layer 2
    gemm2_kernel<<<(NN + 7) / 8, 256>>>(W2, as2, ad2);
    agg2_kernel<<<(NN + 7) / 8, 256>>>(b2, g2, be2, out + 3 * NN);

    // heads
    heads_kernel<<<(NN + 255) / 256, 256>>>(Wc1, bc1, Wc2, bc2, Wr1, br1, Wr2, br2, out);
}

// round 4
// speedup vs baseline: 1.5854x; 1.4038x over previous
#include <cuda_runtime.h>
#include <math.h>

#define NN   50000
#define EE   1600000
#define ET   (EE + NN)
#define INC  256
#define HC   128
#define H1   4
#define C1   32
#define BN_EPS 1e-5f
#define NB   196            // ceil(NN/256)

typedef unsigned long long ull;

// ---------------- scratch ----------------
struct __align__(32) Slot { float w0, w1, w2, w3; int src; int dst; float ea; float pad; };

__device__ float g_xs1 [NN * HC];
__device__ float g_out1[NN * HC];
__device__ float g_xs2 [NN * C1];
__device__ float g_als1[NN * H1];
__device__ float g_ald1[NN * H1];
__device__ float g_als2[NN];
__device__ float g_ald2[NN];
__device__ float g_w2  [ET];
__device__ int   g_deg   [NN];
__device__ int   g_rowptr[NN + 1];
__device__ int   g_cursor[NN];
__device__ int   g_bsum[NB];
__device__ int   g_boff[NB];
__device__ Slot  g_slot[ET];
__device__ float g_partial[512];
__device__ float g_mean;
__device__ float g_k1v[H1];
__device__ float g_k2;

// ---------------- f32x2 helpers ----------------
__device__ __forceinline__ void fma2(ull &d, ull a, ull b) {
    asm("fma.rn.f32x2 %0, %1, %2, %0;" : "+l"(d) : "l"(a), "l"(b));
}
__device__ __forceinline__ ull pack2(float x, float y) {
    ull r; asm("mov.b64 %0, {%1, %2};" : "=l"(r) : "f"(x), "f"(y)); return r;
}
__device__ __forceinline__ float2 unpack2(ull v) {
    float2 f; asm("mov.b64 {%0, %1}, %2;" : "=f"(f.x), "=f"(f.y) : "l"(v)); return f;
}

__device__ __forceinline__ float leaky(float x) { return x > 0.f ? x : 0.2f * x; }
__device__ __forceinline__ float elu(float x)   { return x > 0.f ? x : expm1f(x); }

// ---------------- CSR build ----------------
__global__ void init_deg_kernel() {
    int i = blockIdx.x * blockDim.x + threadIdx.x;
    if (i < NN) g_deg[i] = 1;   // self loop
}

__global__ void hist_mean_kernel(const int* __restrict__ ei, const float* __restrict__ ea) {
    __shared__ float s[256];
    float v = 0.f;
    for (int e = blockIdx.x * blockDim.x + threadIdx.x; e < EE; e += gridDim.x * blockDim.x) {
        atomicAdd(&g_deg[ei[EE + e]], 1);
        v += ea[e];
    }
    s[threadIdx.x] = v; __syncthreads();
    for (int o = 128; o > 0; o >>= 1) {
        if (threadIdx.x < o) s[threadIdx.x] += s[threadIdx.x + o];
        __syncthreads();
    }
    if (threadIdx.x == 0) g_partial[blockIdx.x] = s[0];
}

__global__ void mean_fin_kernel(const float* __restrict__ We1, const float* __restrict__ ae1,
                                const float* __restrict__ We2, const float* __restrict__ ae2) {
    __shared__ float s[512];
    int t = threadIdx.x;
    s[t] = g_partial[t]; __syncthreads();
    for (int o = 256; o > 0; o >>= 1) {
        if (t < o) s[t] += s[t + o];
        __syncthreads();
    }
    if (t == 0) g_mean = s[0] / (float)EE;
    if (t < H1) {
        float k = 0.f;
        for (int c = 0; c < C1; c++) k += We1[t * C1 + c] * ae1[t * C1 + c];
        g_k1v[t] = k;
    }
    if (t == H1) {
        float k = 0.f;
        for (int c = 0; c < C1; c++) k += We2[c] * ae2[c];
        g_k2 = k;
    }
}

// ---- 3-phase parallel scan ----
__global__ void scan_part_kernel() {
    __shared__ int s[256];
    int t = threadIdx.x, b = blockIdx.x;
    int i = b * 256 + t;
    int v = (i < NN) ? g_deg[i] : 0;
    s[t] = v; __syncthreads();
    for (int o = 128; o > 0; o >>= 1) {
        if (t < o) s[t] += s[t + o];
        __syncthreads();
    }
    if (t == 0) g_bsum[b] = s[0];
}

__global__ void scan_mid_kernel() {
    __shared__ int s[256];
    int t = threadIdx.x;
    int v = (t < NB) ? g_bsum[t] : 0;
    s[t] = v; __syncthreads();
    for (int o = 1; o < 256; o <<= 1) {
        int u = (t >= o) ? s[t - o] : 0;
        __syncthreads();
        s[t] += u;
        __syncthreads();
    }
    if (t < NB) g_boff[t] = s[t] - v;   // exclusive
}

__global__ void scan_fin_kernel() {
    __shared__ int s[256];
    int t = threadIdx.x, b = blockIdx.x;
    int i = b * 256 + t;
    int v = (i < NN) ? g_deg[i] : 0;
    s[t] = v; __syncthreads();
    for (int o = 1; o < 256; o <<= 1) {
        int u = (t >= o) ? s[t - o] : 0;
        __syncthreads();
        s[t] += u;
        __syncthreads();
    }
    int excl = s[t] - v + g_boff[b];
    if (i < NN) { g_rowptr[i] = excl; g_cursor[i] = excl; }
    if (b == 0 && t == 0) g_rowptr[NN] = ET;
}

// ---------------- GEMM1: [NN,256] @ [256,128] with f32x2 ----------------
__global__ void sgemm1_kernel(const float* __restrict__ A, const float* __restrict__ B) {
    const int K = INC, Nn = HC;
    __shared__ float As[8][128];
    __shared__ float Bs[8][128];
    int tid  = threadIdx.x;
    int brow = blockIdx.x;
    int trow = (tid / 16) * 8;
    int tcol = (tid % 16) * 8;
    int rowA = tid / 2,  colA = (tid % 2) * 4;
    int rowB = tid / 32, colB = (tid % 32) * 4;
    int ag = brow * 128 + rowA;

    ull acc2[4][8];
#pragma unroll
    for (int p = 0; p < 4; p++)
#pragma unroll
        for (int j = 0; j < 8; j++) acc2[p][j] = 0ULL;

    for (int k0 = 0; k0 < K; k0 += 8) {
        float4 av = make_float4(0.f, 0.f, 0.f, 0.f);
        if (ag < NN) av = *(const float4*)(A + (size_t)ag * K + k0 + colA);
        As[colA + 0][rowA] = av.x;
        As[colA + 1][rowA] = av.y;
        As[colA + 2][rowA] = av.z;
        As[colA + 3][rowA] = av.w;
        float4 bv = *(const float4*)(B + (size_t)(k0 + rowB) * Nn + colB);
        *(float4*)(&Bs[rowB][colB]) = bv;
        __syncthreads();
#pragma unroll
        for (int kk = 0; kk < 8; kk++) {
            ull ar2[4];
#pragma unroll
            for (int p = 0; p < 4; p++) {
                float2 a2 = *(const float2*)(&As[kk][trow + 2 * p]);
                ar2[p] = pack2(a2.x, a2.y);
            }
            ull br2[8];
#pragma unroll
            for (int j = 0; j < 8; j++) {
                float b = Bs[kk][tcol + j];
                br2[j] = pack2(b, b);
            }
#pragma unroll
            for (int p = 0; p < 4; p++)
#pragma unroll
                for (int j = 0; j < 8; j++) fma2(acc2[p][j], ar2[p], br2[j]);
        }
        __syncthreads();
    }
#pragma unroll
    for (int p = 0; p < 4; p++) {
        float c0[8], c1[8];
#pragma unroll
        for (int j = 0; j < 8; j++) {
            float2 v = unpack2(acc2[p][j]);
            c0[j] = v.x; c1[j] = v.y;
        }
        int r = brow * 128 + trow + 2 * p;
        if (r < NN) {
            float* cp = g_xs1 + (size_t)r * Nn + tcol;
            *(float4*)(cp)     = make_float4(c0[0], c0[1], c0[2], c0[3]);
            *(float4*)(cp + 4) = make_float4(c0[4], c0[5], c0[6], c0[7]);
        }
        if (r + 1 < NN) {
            float* cp = g_xs1 + (size_t)(r + 1) * Nn + tcol;
            *(float4*)(cp)     = make_float4(c1[0], c1[1], c1[2], c1[3]);
            *(float4*)(cp + 4) = make_float4(c1[4], c1[5], c1[6], c1[7]);
        }
    }
}

// ---------------- attention coefficients (layer 1), float4 ----------------
__global__ void al1_kernel(const float* __restrict__ as1, const float* __restrict__ ad1) {
    int idx = blockIdx.x * blockDim.x + threadIdx.x;
    if (idx >= NN * H1) return;
    int n = idx >> 2, h = idx & 3;
    const float4* xp = (const float4*)(g_xs1 + (size_t)n * HC + h * C1);
    const float4* ap = (const float4*)(as1 + h * C1);
    const float4* dp = (const float4*)(ad1 + h * C1);
    float s = 0.f, d = 0.f;
#pragma unroll
    for (int c = 0; c < 8; c++) {
        float4 v = xp[c], a = ap[c], b = dp[c];
        s += v.x * a.x + v.y * a.y + v.z * a.z + v.w * a.w;
        d += v.x * b.x + v.y * b.y + v.z * b.z + v.w * b.w;
    }
    g_als1[idx] = s;
    g_ald1[idx] = d;
}

// ---------------- scatter + fused layer-1 softmax weights ----------------
__global__ void scatter_fused_kernel(const int* __restrict__ ei, const float* __restrict__ ea) {
    float mn = g_mean;
    float k0 = g_k1v[0], k1 = g_k1v[1], k2 = g_k1v[2], k3 = g_k1v[3];
    for (int idx = blockIdx.x * blockDim.x + threadIdx.x; idx < ET; idx += gridDim.x * blockDim.x) {
        int srcn, dstn; float eav;
        if (idx < EE) {
            srcn = ei[idx];
            dstn = ei[EE + idx];
            eav  = ea[idx];
        } else {
            srcn = dstn = idx - EE;
            eav  = mn;
        }
        int slot = atomicAdd(&g_cursor[dstn], 1);
        float4 als = *(const float4*)(g_als1 + srcn * 4);
        float4 ald = *(const float4*)(g_ald1 + dstn * 4);
        float4 w;
        w.x = __expf(fminf(leaky(als.x + ald.x + k0 * eav), 80.f));
        w.y = __expf(fminf(leaky(als.y + ald.y + k1 * eav), 80.f));
        w.z = __expf(fminf(leaky(als.z + ald.z + k2 * eav), 80.f));
        w.w = __expf(fminf(leaky(als.w + ald.w + k3 * eav), 80.f));
        float4 meta = make_float4(__int_as_float(srcn), __int_as_float(dstn), eav, 0.f);
        float4* sp = (float4*)&g_slot[slot];
        sp[0] = w;
        sp[1] = meta;
    }
}

// ---------------- agg1: warp per node, all 4 heads; fused bias+bn+elu ----------------
__global__ void agg1_kernel(const float* __restrict__ b1, const float* __restrict__ g1,
                            const float* __restrict__ be1) {
    int n    = (blockIdx.x * blockDim.x + threadIdx.x) >> 5;
    int lane = threadIdx.x & 31;
    if (n >= NN) return;
    int beg = g_rowptr[n], end = g_rowptr[n + 1];

    float acc0 = 0.f, acc1 = 0.f, acc2 = 0.f, acc3 = 0.f;
    float den0 = 0.f, den1 = 0.f, den2 = 0.f, den3 = 0.f;
    int e = beg;
    for (; e + 2 <= end; e += 2) {
        float4 wA = *(const float4*)&g_slot[e];
        float4 wB = *(const float4*)&g_slot[e + 1];
        int sA = ((const int*)&g_slot[e])[4];
        int sB = ((const int*)&g_slot[e + 1])[4];
        const float* xA = g_xs1 + (size_t)sA * HC + lane;
        const float* xB = g_xs1 + (size_t)sB * HC + lane;
        float a0 = xA[0], a1 = xA[32], a2 = xA[64], a3 = xA[96];
        float c0 = xB[0], c1 = xB[32], c2 = xB[64], c3 = xB[96];
        acc0 += wA.x * a0 + wB.x * c0;
        acc1 += wA.y * a1 + wB.y * c1;
        acc2 += wA.z * a2 + wB.z * c2;
        acc3 += wA.w * a3 + wB.w * c3;
        den0 += wA.x + wB.x;
        den1 += wA.y + wB.y;
        den2 += wA.z + wB.z;
        den3 += wA.w + wB.w;
    }
    for (; e < end; ++e) {
        float4 w = *(const float4*)&g_slot[e];
        int s = ((const int*)&g_slot[e])[4];
        const float* xr = g_xs1 + (size_t)s * HC + lane;
        acc0 += w.x * xr[0];  den0 += w.x;
        acc1 += w.y * xr[32]; den1 += w.y;
        acc2 += w.z * xr[64]; den2 += w.z;
        acc3 += w.w * xr[96]; den3 += w.w;
    }
    float inv = rsqrtf(1.f + BN_EPS);
    float* op = g_out1 + (size_t)n * HC + lane;
#pragma unroll
    for (int h = 0; h < 4; h++) {
        float a = (h == 0) ? acc0 : (h == 1) ? acc1 : (h == 2) ? acc2 : acc3;
        float d = (h == 0) ? den0 : (h == 1) ? den1 : (h == 2) ? den2 : den3;
        int c = h * 32 + lane;
        float v = a / (d + 1e-16f) + b1[c];
        v = v * (g1[c] * inv) + be1[c];
        op[h * 32] = elu(v);
    }
}

// ---------------- GEMM2 + fused al2 ----------------
__global__ void gemm2_kernel(const float* __restrict__ W2, const float* __restrict__ as2,
                             const float* __restrict__ ad2) {
    __shared__ float Ws[HC * C1];
    for (int i = threadIdx.x; i < HC * C1; i += blockDim.x) Ws[i] = W2[i];
    __syncthreads();
    int node = blockIdx.x * 8 + threadIdx.x / 32;
    int lane = threadIdx.x & 31;
    if (node >= NN) return;
    const float* row = g_out1 + (size_t)node * HC;
    float s = 0.f;
#pragma unroll 8
    for (int k = 0; k < HC; k++) s += row[k] * Ws[k * C1 + lane];
    g_xs2[(size_t)node * C1 + lane] = s;

    float ps = s * as2[lane];
    float pd = s * ad2[lane];
#pragma unroll
    for (int off = 16; off > 0; off >>= 1) {
        ps += __shfl_xor_sync(0xffffffffu, ps, off);
        pd += __shfl_xor_sync(0xffffffffu, pd, off);
    }
    if (lane == 0) { g_als2[node] = ps; g_ald2[node] = pd; }
}

// ---------------- layer-2 softmax weights (slot-parallel) ----------------
__global__ void logits2_kernel() {
    float k2 = g_k2;
    for (int e = blockIdx.x * blockDim.x + threadIdx.x; e < ET; e += gridDim.x * blockDim.x) {
        float4 meta = ((const float4*)&g_slot[e])[1];
        int src = __float_as_int(meta.x);
        int dst = __float_as_int(meta.y);
        float l = leaky(g_als2[src] + g_ald2[dst] + k2 * meta.z);
        g_w2[e] = __expf(fminf(l, 80.f));
    }
}

// ---------------- agg2: warp per node; fused bias+bn+elu -> hout ----------------
__global__ void agg2_kernel(const float* __restrict__ b2, const float* __restrict__ g2,
                            const float* __restrict__ be2, float* __restrict__ hout) {
    int n    = (blockIdx.x * blockDim.x + threadIdx.x) >> 5;
    int lane = threadIdx.x & 31;
    if (n >= NN) return;
    int beg = g_rowptr[n], end = g_rowptr[n + 1];

    float den = 0.f, acc = 0.f;
    int e = beg;
    for (; e + 2 <= end; e += 2) {
        float wA = g_w2[e], wB = g_w2[e + 1];
        int sA = ((const int*)&g_slot[e])[4];
        int sB = ((const int*)&g_slot[e + 1])[4];
        float xA = g_xs2[(size_t)sA * C1 + lane];
        float xB = g_xs2[(size_t)sB * C1 + lane];
        acc += wA * xA + wB * xB;
        den += wA + wB;
    }
    for (; e < end; ++e) {
        float w = g_w2[e];
        int s = ((const int*)&g_slot[e])[4];
        acc += w * g_xs2[(size_t)s * C1 + lane];
        den += w;
    }
    float v = acc / (den + 1e-16f) + b2[lane];
    v = v * (g2[lane] * rsqrtf(1.f + BN_EPS)) + be2[lane];
    hout[(size_t)n * C1 + lane] = elu(v);
}

// ---------------- heads ----------------
__global__ void heads_kernel(const float* __restrict__ Wc1, const float* __restrict__ bc1,
                             const float* __restrict__ Wc2, const float* __restrict__ bc2,
                             const float* __restrict__ Wr1, const float* __restrict__ br1,
                             const float* __restrict__ Wr2, const float* __restrict__ br2,
                             float* __restrict__ out) {
    __shared__ float sWc1[C1 * 16], sWr1[C1 * 16];
    __shared__ float sWc2[16 * 2], sWr2[16];
    __shared__ float sbc1[16], sbr1[16], sbc2[2], sbr2v[1];
    int t = threadIdx.x;
    for (int i = t; i < C1 * 16; i += blockDim.x) { sWc1[i] = Wc1[i]; sWr1[i] = Wr1[i]; }
    if (t < 32) sWc2[t] = Wc2[t];
    if (t < 16) { sWr2[t] = Wr2[t]; sbc1[t] = bc1[t]; sbr1[t] = br1[t]; }
    if (t < 2)  sbc2[t] = bc2[t];
    if (t == 0) sbr2v[0] = br2[0];
    __syncthreads();

    int n = blockIdx.x * blockDim.x + t;
    if (n >= NN) return;
    const float* hp = out + 3 * NN + (size_t)n * C1;
    float hv[C1];
#pragma unroll
    for (int c = 0; c < C1; c++) hv[c] = hp[c];

    float c0 = sbc2[0], c1 = sbc2[1];
#pragma unroll
    for (int j = 0; j < 16; j++) {
        float tt = sbc1[j];
#pragma unroll
        for (int c = 0; c < C1; c++) tt += hv[c] * sWc1[c * 16 + j];
        tt = fmaxf(tt, 0.f);
        c0 += tt * sWc2[j * 2 + 0];
        c1 += tt * sWc2[j * 2 + 1];
    }
    float r = sbr2v[0];
#pragma unroll
    for (int j = 0; j < 16; j++) {
        float tt = sbr1[j];
#pragma unroll
        for (int c = 0; c < C1; c++) tt += hv[c] * sWr1[c * 16 + j];
        tt = fmaxf(tt, 0.f);
        r += tt * sWr2[j];
    }
    out[(size_t)n * 2 + 0] = c0;
    out[(size_t)n * 2 + 1] = c1;
    out[2 * NN + n] = r;
}

// ---------------- launch ----------------
extern "C" void kernel_launch(void* const* d_in, const int* in_sizes, int n_in,
                              void* d_out, int out_size) {
    const float* x   = (const float*)d_in[0];
    const int*   ei  = (const int*)d_in[1];     // int32 (JAX x64 disabled)
    const float* ea  = (const float*)d_in[2];
    const float* W1  = (const float*)d_in[3];
    const float* as1 = (const float*)d_in[4];
    const float* ad1 = (const float*)d_in[5];
    const float* We1 = (const float*)d_in[6];
    const float* ae1 = (const float*)d_in[7];
    const float* b1  = (const float*)d_in[8];
    const float* g1  = (const float*)d_in[9];
    const float* be1 = (const float*)d_in[10];
    const float* W2  = (const float*)d_in[11];
    const float* as2 = (const float*)d_in[12];
    const float* ad2 = (const float*)d_in[13];
    const float* We2 = (const float*)d_in[14];
    const float* ae2 = (const float*)d_in[15];
    const float* b2  = (const float*)d_in[16];
    const float* g2  = (const float*)d_in[17];
    const float* be2 = (const float*)d_in[18];
    const float* Wc1 = (const float*)d_in[19];
    const float* bc1 = (const float*)d_in[20];
    const float* Wc2 = (const float*)d_in[21];
    const float* bc2 = (const float*)d_in[22];
    const float* Wr1 = (const float*)d_in[23];
    const float* br1 = (const float*)d_in[24];
    const float* Wr2 = (const float*)d_in[25];
    const float* br2 = (const float*)d_in[26];
    float* out = (float*)d_out;

    // degree + mean + scan (parallel)
    init_deg_kernel<<<(NN + 255) / 256, 256>>>();
    hist_mean_kernel<<<512, 256>>>(ei, ea);
    mean_fin_kernel<<<1, 512>>>(We1, ae1, We2, ae2);
    scan_part_kernel<<<NB, 256>>>();
    scan_mid_kernel<<<1, 256>>>();
    scan_fin_kernel<<<NB, 256>>>();

    // layer 1 transform + attention coefficients BEFORE scatter
    sgemm1_kernel<<<(NN + 127) / 128, 256>>>(x, W1);
    al1_kernel<<<(NN * H1 + 255) / 256, 256>>>(as1, ad1);

    // scatter with fused layer-1 softmax weights
    scatter_fused_kernel<<<2048, 256>>>(ei, ea);

    // layer 1 aggregate (+bias+bn+elu)
    agg1_kernel<<<(NN + 7) / 8, 256>>>(b1, g1, be1);

    // layer 2
    gemm2_kernel<<<(NN + 7) / 8, 256>>>(W2, as2, ad2);
    logits2_kernel<<<2048, 256>>>();
    agg2_kernel<<<(NN + 7) / 8, 256>>>(b2, g2, be2, out + 3 * NN);

    // heads
    heads_kernel<<<(NN + 255) / 256, 256>>>(Wc1, bc1, Wc2, bc2, Wr1, br1, Wr2, br2, out);
}